// round 15
// baseline (speedup 1.0000x reference)
#include <cuda_runtime.h>
#include <cuda_fp16.h>
#include <cstdint>
#include <math.h>

// ---------------- problem constants (fixed by dataset) ----------------
#define B_BATCH   2
#define LEN_TOK   5440
#define M_TOK     (B_BATCH * LEN_TOK)   // 10880
#define DMODEL    256
#define NHEAD     8
#define NLVL      4
#define NPT       4
#define DFF       2048

__device__ __constant__ int c_lvlW[4]     = {64, 32, 16, 8};
__device__ __constant__ int c_lvlStart[4] = {0, 4096, 5120, 5376};

// ---------------- scratch (static device globals; no allocation) ------
__device__ __half g_valh[M_TOK * DMODEL];
__device__ float  g_offattn[M_TOK * 384];
__device__ float  g_out2[M_TOK * DMODEL];
__device__ float  g_x   [M_TOK * DMODEL];
__device__ float  g_part[4 * M_TOK * DMODEL];
__device__ __half g_srch[M_TOK * DMODEL];
__device__ __half g_qh  [M_TOK * DMODEL];
__device__ __half g_samph[M_TOK * DMODEL];
__device__ __half g_xh  [M_TOK * DMODEL];
__device__ __half g_ffhh[M_TOK * DFF];
__device__ float  g_boa [384];
__device__ __half g_wvT  [256 * 256];
__device__ __half g_woaT [384 * 256];
__device__ __half g_woutT[256 * 256];
__device__ __half g_w1T  [2048 * 256];
__device__ __half g_w2T  [256 * 2048];

// ---------------- mma / ldmatrix / cp.async helpers ----------------------
__device__ __forceinline__ void mma_f16(float* c, const uint32_t* a, const uint32_t* b) {
    asm volatile(
        "mma.sync.aligned.m16n8k16.row.col.f32.f16.f16.f32 "
        "{%0,%1,%2,%3}, {%4,%5,%6,%7}, {%8,%9}, {%0,%1,%2,%3};\n"
        : "+f"(c[0]), "+f"(c[1]), "+f"(c[2]), "+f"(c[3])
        : "r"(a[0]), "r"(a[1]), "r"(a[2]), "r"(a[3]), "r"(b[0]), "r"(b[1]));
}
__device__ __forceinline__ void ldsm_x4(uint32_t* r, uint32_t addr) {
    asm volatile("ldmatrix.sync.aligned.m8n8.x4.shared.b16 {%0,%1,%2,%3}, [%4];"
                 : "=r"(r[0]), "=r"(r[1]), "=r"(r[2]), "=r"(r[3]) : "r"(addr));
}
__device__ __forceinline__ void cp16(uint32_t saddr, const void* g) {
    asm volatile("cp.async.cg.shared.global [%0], [%1], 16;" :: "r"(saddr), "l"(g));
}
#define CP_COMMIT() asm volatile("cp.async.commit_group;" ::: "memory")
#define CP_WAIT1()  asm volatile("cp.async.wait_group 1;" ::: "memory")
#define CP_WAIT2()  asm volatile("cp.async.wait_group 2;" ::: "memory")

// ---------------- prep: addcvt + all transposes + bias concat ------------
#define PREP_CVT_BLKS  2720
#define PREP_TR_BASE   PREP_CVT_BLKS
#define PREP_BIAS_BLK  (PREP_TR_BASE + 1248)
#define PREP_BLKS      (PREP_BIAS_BLK + 1)

__global__ __launch_bounds__(256)
void prep_kernel(const float4* __restrict__ src4, const float4* __restrict__ pos4,
                 __half2* __restrict__ qh, __half2* __restrict__ srch,
                 const float* __restrict__ wv, const float* __restrict__ woff,
                 const float* __restrict__ wattn, const float* __restrict__ wout,
                 const float* __restrict__ w1, const float* __restrict__ w2,
                 __half* __restrict__ wvT, __half* __restrict__ woaT,
                 __half* __restrict__ woutT,
                 __half* __restrict__ w1T, __half* __restrict__ w2T,
                 const float* __restrict__ b_off, const float* __restrict__ b_attn,
                 float* __restrict__ boa)
{
    const int bid = blockIdx.x;
    const int t = threadIdx.x;

    if (bid < PREP_CVT_BLKS) {
        const int i = bid * 256 + t;
        float4 s = src4[i], p = pos4[i];
        srch[2 * i]     = __floats2half2_rn(s.x, s.y);
        srch[2 * i + 1] = __floats2half2_rn(s.z, s.w);
        qh[2 * i]       = __floats2half2_rn(s.x + p.x, s.y + p.y);
        qh[2 * i + 1]   = __floats2half2_rn(s.z + p.z, s.w + p.w);
        return;
    }
    if (bid == PREP_BIAS_BLK) {
        if (t < 256) boa[t] = b_off[t];
        if (t < 128) boa[256 + t] = b_attn[t];
        return;
    }
    const int tb = bid - PREP_TR_BASE;
    const float* in; __half* out; int R, C, tix;
    if      (tb < 64)  { in = wv;    out = wvT;            R = 256;  C = 256;  tix = tb; }
    else if (tb < 128) { in = woff;  out = woaT;           R = 256;  C = 256;  tix = tb - 64; }
    else if (tb < 160) { in = wattn; out = woaT + 256*256; R = 256;  C = 128;  tix = tb - 128; }
    else if (tb < 224) { in = wout;  out = woutT;          R = 256;  C = 256;  tix = tb - 160; }
    else if (tb < 736) { in = w1;    out = w1T;            R = 256;  C = 2048; tix = tb - 224; }
    else               { in = w2;    out = w2T;            R = 2048; C = 256;  tix = tb - 736; }
    const int tilesX = C / 32;
    const int c0 = (tix % tilesX) * 32, r0 = (tix / tilesX) * 32;

    __shared__ float tile[32][33];
    const int x = t & 31, y = t >> 5;
#pragma unroll
    for (int i = 0; i < 32; i += 8)
        tile[y + i][x] = in[(size_t)(r0 + y + i) * C + c0 + x];
    __syncthreads();
#pragma unroll
    for (int i = 0; i < 32; i += 8)
        out[(size_t)(c0 + y + i) * R + r0 + x] = __float2half_rn(tile[x][y + i]);
}

// ---------------- fp16 mma.sync GEMM body: BK=32, 4-stage cp.async -------
// CTA 128x128, 256 thr = 8 warps (2m x 4n), warp tile 64x32.
// MODE: 0 +bias, 1 +bias+relu, 2 raw partial. Requires kLen % 128 == 0.
#define LDH      40
#define OP_HALVES (128 * LDH)
#define ABYTES   (OP_HALVES * 2)          // 10240
#define STAGEB   (2 * ABYTES)             // 20480
#define NSTAGE   4
#define SMBYTES  (NSTAGE * STAGEB)        // 81920

template <int MODE, typename OutT>
__device__ __forceinline__
void gemm_body(const __half* __restrict__ A, int lda,
               const __half* __restrict__ BT, int ldb,
               OutT* __restrict__ C, int ldc,
               const float* __restrict__ bias, int kLen,
               __half* sm, int m0, int n0)
{
    const int t    = threadIdx.x;
    const int warp = t >> 5;
    const int lane = t & 31;
    const int wm   = warp >> 2;
    const int wn   = warp & 3;
    const int g    = lane >> 2;
    const int tq   = lane & 3;

    const uint32_t sbase = (uint32_t)__cvta_generic_to_shared(sm);

    // staging: per stage, per operand: 512 x 16B chunks; 2 chunks/thread
    const int r0c = t >> 2, r1c = (t + 256) >> 2;
    const int ccol = (t & 3) * 8;

    const int rA = ((lane >> 3) & 1) * 8 + (lane & 7);
    const int cA = (lane >> 4) * 8;
    const int rB = ((lane >> 4) & 1) * 8 + (lane & 7);
    const int cB = ((lane >> 3) & 1) * 8;

    float acc[4][4][4];
#pragma unroll
    for (int a_ = 0; a_ < 4; a_++)
#pragma unroll
        for (int b_ = 0; b_ < 4; b_++)
#pragma unroll
            for (int c_ = 0; c_ < 4; c_++) acc[a_][b_][c_] = 0.f;

    const int KT = kLen >> 5;   // k-tiles of 32 (>= 8 for all calls)

    // prologue: stages 0..2
#pragma unroll
    for (int s = 0; s < 3; s++) {
        const int kb = s * 32;
        const uint32_t sb = sbase + s * STAGEB;
        cp16(sb + (uint32_t)((r0c * LDH + ccol) * 2),          &A [(size_t)(m0 + r0c) * lda + kb + ccol]);
        cp16(sb + (uint32_t)((r1c * LDH + ccol) * 2),          &A [(size_t)(m0 + r1c) * lda + kb + ccol]);
        cp16(sb + ABYTES + (uint32_t)((r0c * LDH + ccol) * 2), &BT[(size_t)(n0 + r0c) * ldb + kb + ccol]);
        cp16(sb + ABYTES + (uint32_t)((r1c * LDH + ccol) * 2), &BT[(size_t)(n0 + r1c) * ldb + kb + ccol]);
        CP_COMMIT();
    }

    for (int kt = 0; kt < KT; kt++) {
        CP_WAIT2();          // stage kt complete (kt+1, kt+2 may stay in flight)
        __syncthreads();     // stage kt visible to all; compute on (kt+1)%4 buf done last iter

        const int nkt = kt + 3;
        if (nkt < KT) {
            const int kb = nkt * 32;
            const uint32_t sb = sbase + (nkt & 3) * STAGEB;
            cp16(sb + (uint32_t)((r0c * LDH + ccol) * 2),          &A [(size_t)(m0 + r0c) * lda + kb + ccol]);
            cp16(sb + (uint32_t)((r1c * LDH + ccol) * 2),          &A [(size_t)(m0 + r1c) * lda + kb + ccol]);
            cp16(sb + ABYTES + (uint32_t)((r0c * LDH + ccol) * 2), &BT[(size_t)(n0 + r0c) * ldb + kb + ccol]);
            cp16(sb + ABYTES + (uint32_t)((r1c * LDH + ccol) * 2), &BT[(size_t)(n0 + r1c) * ldb + kb + ccol]);
        }
        CP_COMMIT();         // always commit (uniform group accounting)

        // compute on stage kt
        const uint32_t aBuf = sbase + (kt & 3) * STAGEB;
        const uint32_t bBuf = aBuf + ABYTES;
#pragma unroll
        for (int kq = 0; kq < 2; kq++) {
            uint32_t bf[2][4];
#pragma unroll
            for (int p = 0; p < 2; p++)
                ldsm_x4(bf[p], bBuf + (uint32_t)(((wn * 32 + p * 16 + rB) * LDH + kq * 16 + cB) * 2));
            uint32_t af[4][4];
#pragma unroll
            for (int mt = 0; mt < 4; mt++)
                ldsm_x4(af[mt], aBuf + (uint32_t)(((wm * 64 + mt * 16 + rA) * LDH + kq * 16 + cA) * 2));
#pragma unroll
            for (int mt = 0; mt < 4; mt++)
#pragma unroll
                for (int p = 0; p < 2; p++) {
                    mma_f16(acc[mt][2 * p],     af[mt], &bf[p][0]);
                    mma_f16(acc[mt][2 * p + 1], af[mt], &bf[p][2]);
                }
        }
    }

#pragma unroll
    for (int mt = 0; mt < 4; mt++) {
        const int row = m0 + wm * 64 + mt * 16 + g;
#pragma unroll
        for (int nt = 0; nt < 4; nt++) {
            const int col = n0 + wn * 32 + nt * 8 + tq * 2;
            float bx = 0.f, by = 0.f;
            if (MODE < 2) { float2 bb = *(const float2*)&bias[col]; bx = bb.x; by = bb.y; }
            float v0 = acc[mt][nt][0] + bx;
            float v1 = acc[mt][nt][1] + by;
            float v2 = acc[mt][nt][2] + bx;
            float v3 = acc[mt][nt][3] + by;
            if (MODE == 1) {
                v0 = fmaxf(v0, 0.f); v1 = fmaxf(v1, 0.f);
                v2 = fmaxf(v2, 0.f); v3 = fmaxf(v3, 0.f);
            }
            if constexpr (sizeof(OutT) == 2) {
                *(__half2*)&C[(size_t)row * ldc + col]       = __floats2half2_rn(v0, v1);
                *(__half2*)&C[(size_t)(row + 8) * ldc + col] = __floats2half2_rn(v2, v3);
            } else {
                *(float2*)&C[(size_t)row * ldc + col]       = make_float2(v0, v1);
                *(float2*)&C[(size_t)(row + 8) * ldc + col] = make_float2(v2, v3);
            }
        }
    }
}

template <int MODE, typename OutT>
__global__ __launch_bounds__(256, 2)
void gemm_mma(const __half* __restrict__ A, int lda,
              const __half* __restrict__ BT, int ldb,
              OutT* __restrict__ C, int ldc, size_t cSlice,
              const float* __restrict__ bias, int kLen)
{
    extern __shared__ __align__(16) __half sm[];
    gemm_body<MODE, OutT>(A + (size_t)blockIdx.z * kLen, lda,
                          BT + (size_t)blockIdx.z * kLen, ldb,
                          C + (size_t)blockIdx.z * cSlice, ldc,
                          bias, kLen, sm, blockIdx.y * 128, blockIdx.x * 128);
}

// dual projection: bx 0..1 -> value proj (fp16 out), bx 2..4 -> off+attn (fp32)
__global__ __launch_bounds__(256, 2)
void gemm_dual(const __half* __restrict__ srch, const __half* __restrict__ qh,
               const __half* __restrict__ wvT, const __half* __restrict__ woaT,
               __half* __restrict__ valh, float* __restrict__ offattn,
               const float* __restrict__ b_value, const float* __restrict__ boa)
{
    extern __shared__ __align__(16) __half sm[];
    const int bx = blockIdx.x;
    const int m0 = blockIdx.y * 128;
    if (bx < 2) {
        gemm_body<0, __half>(srch, 256, wvT, 256, valh, 256, b_value, 256,
                             sm, m0, bx * 128);
    } else {
        gemm_body<0, float>(qh, 256, woaT, 256, offattn, 384, boa, 256,
                            sm, m0, (bx - 2) * 128);
    }
}

// ---------------- 128x64 GEMM (R6-proven body), 3 CTAs/SM ---------------
#define LDH6      40
#define ABYTES6   (128 * LDH6 * 2)        // 10240
#define STAGEB6   (ABYTES6 + 64 * LDH6 * 2) // 15360
#define SMBYTES6  (3 * STAGEB6)           // 46080

__global__ __launch_bounds__(256, 3)
void gemm64_bias(const __half* __restrict__ A, int lda,
                 const __half* __restrict__ BT, int ldb,
                 float* __restrict__ C, int ldc,
                 const float* __restrict__ bias, int kLen)
{
    extern __shared__ __align__(16) __half sm6[];
    const uint32_t sbase = (uint32_t)__cvta_generic_to_shared(sm6);

    const int t    = threadIdx.x;
    const int warp = t >> 5;
    const int lane = t & 31;
    const int wm   = warp & 3;
    const int wn   = warp >> 2;
    const int g    = lane >> 2;
    const int tq   = lane & 3;
    const int m0 = blockIdx.y * 128;
    const int n0 = blockIdx.x * 64;

    const int ar0 = t >> 2, ac = (t & 3) * 8;

    const int rA = ((lane >> 3) & 1) * 8 + (lane & 7);
    const int cA = (lane >> 4) * 8;
    const int rB = ((lane >> 4) & 1) * 8 + (lane & 7);
    const int cB = ((lane >> 3) & 1) * 8;

    float acc[2][4][4];
#pragma unroll
    for (int a_ = 0; a_ < 2; a_++)
#pragma unroll
        for (int b_ = 0; b_ < 4; b_++)
#pragma unroll
            for (int c_ = 0; c_ < 4; c_++) acc[a_][b_][c_] = 0.f;

    const int KT = kLen >> 5;

#pragma unroll
    for (int s = 0; s < 2; s++) {
        const int kb = s * 32;
        const uint32_t sb = sbase + s * STAGEB6;
        cp16(sb + (uint32_t)((ar0 * LDH6 + ac) * 2),
             &A[(size_t)(m0 + ar0) * lda + kb + ac]);
        cp16(sb + (uint32_t)(((ar0 + 64) * LDH6 + ac) * 2),
             &A[(size_t)(m0 + ar0 + 64) * lda + kb + ac]);
        cp16(sb + ABYTES6 + (uint32_t)((ar0 * LDH6 + ac) * 2),
             &BT[(size_t)(n0 + ar0) * ldb + kb + ac]);
        CP_COMMIT();
    }

    for (int kt = 0; kt < KT; kt++) {
        CP_WAIT1();
        __syncthreads();

        const int nkt = kt + 2;
        if (nkt < KT) {
            const int kb = nkt * 32;
            const uint32_t sb = sbase + (nkt % 3) * STAGEB6;
            cp16(sb + (uint32_t)((ar0 * LDH6 + ac) * 2),
                 &A[(size_t)(m0 + ar0) * lda + kb + ac]);
            cp16(sb + (uint32_t)(((ar0 + 64) * LDH6 + ac) * 2),
                 &A[(size_t)(m0 + ar0 + 64) * lda + kb + ac]);
            cp16(sb + ABYTES6 + (uint32_t)((ar0 * LDH6 + ac) * 2),
                 &BT[(size_t)(n0 + ar0) * ldb + kb + ac]);
        }
        CP_COMMIT();

        const uint32_t aBuf = sbase + (kt % 3) * STAGEB6;
        const uint32_t bBuf = aBuf + ABYTES6;
#pragma unroll
        for (int kq = 0; kq < 2; kq++) {
            uint32_t af[2][4], bf[2][4];
#pragma unroll
            for (int mt = 0; mt < 2; mt++)
                ldsm_x4(af[mt], aBuf + (uint32_t)(((wm * 32 + mt * 16 + rA) * LDH6 + kq * 16 + cA) * 2));
#pragma unroll
            for (int p = 0; p < 2; p++)
                ldsm_x4(bf[p], bBuf + (uint32_t)(((wn * 32 + p * 16 + rB) * LDH6 + kq * 16 + cB) * 2));
#pragma unroll
            for (int mt = 0; mt < 2; mt++)
#pragma unroll
                for (int p = 0; p < 2; p++) {
                    mma_f16(acc[mt][2 * p],     af[mt], &bf[p][0]);
                    mma_f16(acc[mt][2 * p + 1], af[mt], &bf[p][2]);
                }
        }
    }

#pragma unroll
    for (int mt = 0; mt < 2; mt++) {
        const int row = m0 + wm * 32 + mt * 16 + g;
#pragma unroll
        for (int nt = 0; nt < 4; nt++) {
            const int col = n0 + wn * 32 + nt * 8 + tq * 2;
            float2 bb = *(const float2*)&bias[col];
            *(float2*)&C[(size_t)row * ldc + col] =
                make_float2(acc[mt][nt][0] + bb.x, acc[mt][nt][1] + bb.y);
            *(float2*)&C[(size_t)(row + 8) * ldc + col] =
                make_float2(acc[mt][nt][2] + bb.x, acc[mt][nt][3] + bb.y);
        }
    }
}

// ---------------- deformable sampling: precompute + gather (packed) ------
__global__ __launch_bounds__(256)
void sample_kernel(const __half* __restrict__ value,
                   const float* __restrict__ oa,
                   __half* __restrict__ samp)
{
    __shared__ int2 sWI[8][64];

    const int m    = blockIdx.x;
    const int h    = threadIdx.x >> 5;
    const int lane = threadIdx.x & 31;
    const int b    = m / LEN_TOK;
    const int qi   = m - b * LEN_TOK;

    int Wq, idx;
    if      (qi < 4096) { Wq = 64; idx = qi; }
    else if (qi < 5120) { Wq = 32; idx = qi - 4096; }
    else if (qi < 5376) { Wq = 16; idx = qi - 5120; }
    else                { Wq = 8;  idx = qi - 5376; }
    const int   row = idx / Wq;
    const int   col = idx - row * Wq;
    const float rx  = (col + 0.5f) / (float)Wq;
    const float ry  = (row + 0.5f) / (float)Wq;

    const float offv = oa[(size_t)m * 384 + h * 32 + lane];

    float logit = (lane < 16) ? oa[(size_t)m * 384 + 256 + h * 16 + lane] : -1e30f;
    float mx = logit;
#pragma unroll
    for (int s = 8; s > 0; s >>= 1) mx = fmaxf(mx, __shfl_xor_sync(0xffffffffu, mx, s));
    float e = (lane < 16) ? expf(logit - mx) : 0.0f;
    float sm = e;
#pragma unroll
    for (int s = 8; s > 0; s >>= 1) sm += __shfl_xor_sync(0xffffffffu, sm, s);
    const float prob = e / sm;

    const int pt = lane & 15;
    const float a  = __shfl_sync(0xffffffffu, prob, pt);
    const float ox = __shfl_sync(0xffffffffu, offv, 2 * pt);
    const float oy = __shfl_sync(0xffffffffu, offv, 2 * pt + 1);
    if (lane < 16) {
        const int   l  = pt >> 2;
        const int   Wl = c_lvlW[l];
        const float Wf = (float)Wl;
        const float x = rx * Wf + ox - 0.5f;
        const float y = ry * Wf + oy - 0.5f;
        const float x0f = floorf(x), y0f = floorf(y);
        const float dx = x - x0f, dy = y - y0f;
        const int x0 = (int)x0f, y0 = (int)y0f;
        const int x1 = x0 + 1,   y1 = y0 + 1;
        const float wx0 = ((x0 >= 0) & (x0 < Wl)) ? (1.f - dx) : 0.f;
        const float wx1 = ((x1 >= 0) & (x1 < Wl)) ? dx : 0.f;
        const float wy0 = ((y0 >= 0) & (y0 < Wl)) ? (1.f - dy) : 0.f;
        const float wy1 = ((y1 >= 0) & (y1 < Wl)) ? dy : 0.f;
        const int x0c = min(max(x0, 0), Wl - 1), x1c = min(max(x1, 0), Wl - 1);
        const int y0c = min(max(y0, 0), Wl - 1), y1c = min(max(y1, 0), Wl - 1);
        const int base = c_lvlStart[l];
        sWI[h][pt * 4 + 0] = make_int2(base + y0c * Wl + x0c, __float_as_int(wx0 * wy0 * a));
        sWI[h][pt * 4 + 1] = make_int2(base + y0c * Wl + x1c, __float_as_int(wx1 * wy0 * a));
        sWI[h][pt * 4 + 2] = make_int2(base + y1c * Wl + x0c, __float_as_int(wx0 * wy1 * a));
        sWI[h][pt * 4 + 3] = make_int2(base + y1c * Wl + x1c, __float_as_int(wx1 * wy1 * a));
    }
    __syncwarp();

    const int tap = lane >> 3;
    const int c4  = lane & 7;
    const __half* vb = value + ((size_t)b * LEN_TOK) * 256 + h * 32 + c4 * 4;

    float4 acc = make_float4(0.f, 0.f, 0.f, 0.f);
#pragma unroll
    for (int p = 0; p < 16; p++) {
        const int2  wi = sWI[h][p * 4 + tap];
        const float w  = __int_as_float(wi.y);
        const uint2 raw = *(const uint2*)&vb[(size_t)wi.x * 256];
        const float2 v01 = __half22float2(*(const __half2*)&raw.x);
        const float2 v23 = __half22float2(*(const __half2*)&raw.y);
        acc.x = fmaf(w, v01.x, acc.x);
        acc.y = fmaf(w, v01.y, acc.y);
        acc.z = fmaf(w, v23.x, acc.z);
        acc.w = fmaf(w, v23.y, acc.w);
    }
#pragma unroll
    for (int s = 8; s <= 16; s <<= 1) {
        acc.x += __shfl_xor_sync(0xffffffffu, acc.x, s);
        acc.y += __shfl_xor_sync(0xffffffffu, acc.y, s);
        acc.z += __shfl_xor_sync(0xffffffffu, acc.z, s);
        acc.w += __shfl_xor_sync(0xffffffffu, acc.w, s);
    }
    if (lane < 8) {
        __half* dst = &samp[(size_t)m * 256 + h * 32 + c4 * 4];
        *(__half2*)&dst[0] = __floats2half2_rn(acc.x, acc.y);
        *(__half2*)&dst[2] = __floats2half2_rn(acc.z, acc.w);
    }
}

// ---------------- fused residual-add + LayerNorm (fp32 + fp16 out) ------
__global__ __launch_bounds__(256)
void add_ln_kernel(const float* __restrict__ A, const float* __restrict__ Bv,
                   const float* __restrict__ gamma, const float* __restrict__ beta,
                   float* __restrict__ out, __half* __restrict__ outh)
{
    const int m = blockIdx.x;
    const int t = threadIdx.x;
    const float v = A[(size_t)m * 256 + t] + Bv[(size_t)m * 256 + t];

    float s = v, q2 = v * v;
#pragma unroll
    for (int sft = 16; sft > 0; sft >>= 1) {
        s  += __shfl_xor_sync(0xffffffffu, s,  sft);
        q2 += __shfl_xor_sync(0xffffffffu, q2, sft);
    }
    __shared__ float ws[8], wq[8], mv[2];
    const int wid = t >> 5, lane = t & 31;
    if (lane == 0) { ws[wid] = s; wq[wid] = q2; }
    __syncthreads();
    if (t == 0) {
        float ts = 0.f, tq_ = 0.f;
#pragma unroll
        for (int i = 0; i < 8; i++) { ts += ws[i]; tq_ += wq[i]; }
        const float mean = ts * (1.0f / 256.0f);
        const float var  = tq_ * (1.0f / 256.0f) - mean * mean;
        mv[0] = mean;
        mv[1] = rsqrtf(var + 1e-5f);
    }
    __syncthreads();
    const float o = (v - mv[0]) * mv[1] * gamma[t] + beta[t];
    out[(size_t)m * 256 + t]  = o;
    outh[(size_t)m * 256 + t] = __float2half_rn(o);
}

// ---- fused: 4 FFN2 partials + b2 + residual + LayerNorm ----------------
__global__ __launch_bounds__(256)
void add4_ln_kernel(const float* __restrict__ X, const float* __restrict__ P,
                    const float* __restrict__ bias,
                    const float* __restrict__ gamma, const float* __restrict__ beta,
                    float* __restrict__ out)
{
    const int m = blockIdx.x;
    const int t = threadIdx.x;
    const size_t i = (size_t)m * 256 + t;
    const size_t sl = (size_t)M_TOK * 256;
    const float v = X[i] + P[i] + P[i + sl] + P[i + 2 * sl] + P[i + 3 * sl] + bias[t];

    float s = v, q2 = v * v;
#pragma unroll
    for (int sft = 16; sft > 0; sft >>= 1) {
        s  += __shfl_xor_sync(0xffffffffu, s,  sft);
        q2 += __shfl_xor_sync(0xffffffffu, q2, sft);
    }
    __shared__ float ws[8], wq[8], mv[2];
    const int wid = t >> 5, lane = t & 31;
    if (lane == 0) { ws[wid] = s; wq[wid] = q2; }
    __syncthreads();
    if (t == 0) {
        float ts = 0.f, tq_ = 0.f;
#pragma unroll
        for (int ii = 0; ii < 8; ii++) { ts += ws[ii]; tq_ += wq[ii]; }
        const float mean = ts * (1.0f / 256.0f);
        const float var  = tq_ * (1.0f / 256.0f) - mean * mean;
        mv[0] = mean;
        mv[1] = rsqrtf(var + 1e-5f);
    }
    __syncthreads();
    out[i] = (v - mv[0]) * mv[1] * gamma[t] + beta[t];
}

// ---------------- launch -------------------------------------------------
template <typename T>
static inline T* sym(const void* s)
{
    void* p = nullptr;
    cudaGetSymbolAddress(&p, s);
    return (T*)p;
}

extern "C" void kernel_launch(void* const* d_in, const int* in_sizes, int n_in,
                              void* d_out, int out_size)
{
    const float* src     = (const float*)d_in[0];
    const float* pos     = (const float*)d_in[1];
    const float* w_value = (const float*)d_in[4];
    const float* b_value = (const float*)d_in[5];
    const float* w_off   = (const float*)d_in[6];
    const float* b_off   = (const float*)d_in[7];
    const float* w_attn  = (const float*)d_in[8];
    const float* b_attn  = (const float*)d_in[9];
    const float* w_out   = (const float*)d_in[10];
    const float* b_out   = (const float*)d_in[11];
    const float* w1      = (const float*)d_in[12];
    const float* b1      = (const float*)d_in[13];
    const float* w2      = (const float*)d_in[14];
    const float* b2      = (const float*)d_in[15];
    const float* g1      = (const float*)d_in[16];
    const float* be1     = (const float*)d_in[17];
    const float* g2      = (const float*)d_in[18];
    const float* be2     = (const float*)d_in[19];
    float* out = (float*)d_out;

    __half* valh    = sym<__half>(g_valh);
    float*  offattn = sym<float>(g_offattn);
    float*  out2    = sym<float>(g_out2);
    float*  x       = sym<float>(g_x);
    float*  part    = sym<float>(g_part);
    float*  boa     = sym<float>(g_boa);
    __half* srch    = sym<__half>(g_srch);
    __half* qh      = sym<__half>(g_qh);
    __half* samph   = sym<__half>(g_samph);
    __half* xh      = sym<__half>(g_xh);
    __half* ffhh    = sym<__half>(g_ffhh);
    __half* wvT     = sym<__half>(g_wvT);
    __half* woaT    = sym<__half>(g_woaT);
    __half* woutT   = sym<__half>(g_woutT);
    __half* w1T     = sym<__half>(g_w1T);
    __half* w2T     = sym<__half>(g_w2T);

    cudaFuncSetAttribute(gemm_mma<1, __half>, cudaFuncAttributeMaxDynamicSharedMemorySize, SMBYTES);
    cudaFuncSetAttribute(gemm_mma<2, float>,  cudaFuncAttributeMaxDynamicSharedMemorySize, SMBYTES);
    cudaFuncSetAttribute(gemm_dual,           cudaFuncAttributeMaxDynamicSharedMemorySize, SMBYTES);

    // prep: addcvt (2720) + transposes (1248) + bias concat (1)
    prep_kernel<<<PREP_BLKS, 256>>>((const float4*)src, (const float4*)pos,
                                    (__half2*)qh, (__half2*)srch,
                                    w_value, w_off, w_attn, w_out, w1, w2,
                                    wvT, woaT, woutT, w1T, w2T,
                                    b_off, b_attn, boa);

    // value proj (fp16 out) + off/attn proj (fp32 out), one launch
    gemm_dual<<<dim3(5, M_TOK / 128), 256, SMBYTES>>>(srch, qh, wvT, woaT,
                                                      valh, offattn, b_value, boa);

    // deformable sampling (softmax fused, precompute+gather)
    sample_kernel<<<M_TOK, 256>>>(valh, offattn, samph);

    // output projection: 128x64 tiles, 3 CTAs/SM
    gemm64_bias<<<dim3(4, M_TOK / 128), 256, SMBYTES6>>>(
        samph, 256, woutT, 256, out2, 256, b_out, 256);

    // x = LN(src + out2)
    add_ln_kernel<<<M_TOK, 256>>>(src, out2, g1, be1, x, xh);

    // FFN1: relu(x @ w1 + b1), fp16 out
    gemm_mma<1, __half><<<dim3(16, M_TOK / 128), 256, SMBYTES>>>(
        xh, 256, w1T, 256, ffhh, DFF, 0, b1, 256);

    // FFN2: split-K=4 partials (kLen=512 each)
    gemm_mma<2, float><<<dim3(2, M_TOK / 128, 4), 256, SMBYTES>>>(
        ffhh, DFF, w2T, DFF, part, 256, (size_t)M_TOK * 256, nullptr, 512);

    // out = LN(x + sum(parts) + b2)
    add4_ln_kernel<<<M_TOK, 256>>>(x, part, b2, g2, be2, out);
}

// round 16
// speedup vs baseline: 1.0873x; 1.0873x over previous
#include <cuda_runtime.h>
#include <cuda_fp16.h>
#include <cstdint>
#include <math.h>

// ---------------- problem constants (fixed by dataset) ----------------
#define B_BATCH   2
#define LEN_TOK   5440
#define M_TOK     (B_BATCH * LEN_TOK)   // 10880
#define DMODEL    256
#define NHEAD     8
#define NLVL      4
#define NPT       4
#define DFF       2048

__device__ __constant__ int c_lvlW[4]     = {64, 32, 16, 8};
__device__ __constant__ int c_lvlStart[4] = {0, 4096, 5120, 5376};

// ---------------- scratch (static device globals; no allocation) ------
__device__ __half g_valh[M_TOK * DMODEL];
__device__ float  g_offattn[M_TOK * 384];
__device__ float  g_out2[M_TOK * DMODEL];
__device__ float  g_x   [M_TOK * DMODEL];
__device__ float  g_part[4 * M_TOK * DMODEL];
__device__ __half g_srch[M_TOK * DMODEL];
__device__ __half g_qh  [M_TOK * DMODEL];
__device__ __half g_samph[M_TOK * DMODEL];
__device__ __half g_xh  [M_TOK * DMODEL];
__device__ __half g_ffhh[M_TOK * DFF];
__device__ float  g_boa [384];
__device__ __half g_wvT  [256 * 256];
__device__ __half g_woaT [384 * 256];
__device__ __half g_woutT[256 * 256];
__device__ __half g_w1T  [2048 * 256];
__device__ __half g_w2T  [256 * 2048];

// ---------------- mma / ldmatrix / cp.async helpers ----------------------
__device__ __forceinline__ void mma_f16(float* c, const uint32_t* a, const uint32_t* b) {
    asm volatile(
        "mma.sync.aligned.m16n8k16.row.col.f32.f16.f16.f32 "
        "{%0,%1,%2,%3}, {%4,%5,%6,%7}, {%8,%9}, {%0,%1,%2,%3};\n"
        : "+f"(c[0]), "+f"(c[1]), "+f"(c[2]), "+f"(c[3])
        : "r"(a[0]), "r"(a[1]), "r"(a[2]), "r"(a[3]), "r"(b[0]), "r"(b[1]));
}
__device__ __forceinline__ void ldsm_x4(uint32_t* r, uint32_t addr) {
    asm volatile("ldmatrix.sync.aligned.m8n8.x4.shared.b16 {%0,%1,%2,%3}, [%4];"
                 : "=r"(r[0]), "=r"(r[1]), "=r"(r[2]), "=r"(r[3]) : "r"(addr));
}
__device__ __forceinline__ void cp16(uint32_t saddr, const void* g) {
    asm volatile("cp.async.cg.shared.global [%0], [%1], 16;" :: "r"(saddr), "l"(g));
}
#define CP_COMMIT() asm volatile("cp.async.commit_group;" ::: "memory")
#define CP_WAIT1()  asm volatile("cp.async.wait_group 1;" ::: "memory")

// ---------------- prep: addcvt + all transposes + bias concat ------------
#define PREP_CVT_BLKS  2720
#define PREP_TR_BASE   PREP_CVT_BLKS
#define PREP_BIAS_BLK  (PREP_TR_BASE + 1248)
#define PREP_BLKS      (PREP_BIAS_BLK + 1)

__global__ __launch_bounds__(256)
void prep_kernel(const float4* __restrict__ src4, const float4* __restrict__ pos4,
                 __half2* __restrict__ qh, __half2* __restrict__ srch,
                 const float* __restrict__ wv, const float* __restrict__ woff,
                 const float* __restrict__ wattn, const float* __restrict__ wout,
                 const float* __restrict__ w1, const float* __restrict__ w2,
                 __half* __restrict__ wvT, __half* __restrict__ woaT,
                 __half* __restrict__ woutT,
                 __half* __restrict__ w1T, __half* __restrict__ w2T,
                 const float* __restrict__ b_off, const float* __restrict__ b_attn,
                 float* __restrict__ boa)
{
    const int bid = blockIdx.x;
    const int t = threadIdx.x;

    if (bid < PREP_CVT_BLKS) {
        const int i = bid * 256 + t;
        float4 s = src4[i], p = pos4[i];
        srch[2 * i]     = __floats2half2_rn(s.x, s.y);
        srch[2 * i + 1] = __floats2half2_rn(s.z, s.w);
        qh[2 * i]       = __floats2half2_rn(s.x + p.x, s.y + p.y);
        qh[2 * i + 1]   = __floats2half2_rn(s.z + p.z, s.w + p.w);
        return;
    }
    if (bid == PREP_BIAS_BLK) {
        if (t < 256) boa[t] = b_off[t];
        if (t < 128) boa[256 + t] = b_attn[t];
        return;
    }
    const int tb = bid - PREP_TR_BASE;
    const float* in; __half* out; int R, C, tix;
    if      (tb < 64)  { in = wv;    out = wvT;            R = 256;  C = 256;  tix = tb; }
    else if (tb < 128) { in = woff;  out = woaT;           R = 256;  C = 256;  tix = tb - 64; }
    else if (tb < 160) { in = wattn; out = woaT + 256*256; R = 256;  C = 128;  tix = tb - 128; }
    else if (tb < 224) { in = wout;  out = woutT;          R = 256;  C = 256;  tix = tb - 160; }
    else if (tb < 736) { in = w1;    out = w1T;            R = 256;  C = 2048; tix = tb - 224; }
    else               { in = w2;    out = w2T;            R = 2048; C = 256;  tix = tb - 736; }
    const int tilesX = C / 32;
    const int c0 = (tix % tilesX) * 32, r0 = (tix / tilesX) * 32;

    __shared__ float tile[32][33];
    const int x = t & 31, y = t >> 5;
#pragma unroll
    for (int i = 0; i < 32; i += 8)
        tile[y + i][x] = in[(size_t)(r0 + y + i) * C + c0 + x];
    __syncthreads();
#pragma unroll
    for (int i = 0; i < 32; i += 8)
        out[(size_t)(c0 + y + i) * R + r0 + x] = __float2half_rn(tile[x][y + i]);
}

// ---------------- fp16 mma.sync GEMM body: BK=64, 3-stage (R14-proven) ---
#define LDH      72
#define OP_HALVES (128 * LDH)
#define ABYTES   (OP_HALVES * 2)         // 18432
#define STAGEB   (2 * ABYTES)            // 36864
#define NSTAGE   3
#define SMBYTES  (NSTAGE * STAGEB)       // 110592

template <int MODE, typename OutT>
__device__ __forceinline__
void gemm_body(const __half* __restrict__ A, int lda,
               const __half* __restrict__ BT, int ldb,
               OutT* __restrict__ C, int ldc,
               const float* __restrict__ bias, int kLen,
               __half* sm, int m0, int n0)
{
    const int t    = threadIdx.x;
    const int warp = t >> 5;
    const int lane = t & 31;
    const int wm   = warp >> 2;
    const int wn   = warp & 3;
    const int g    = lane >> 2;
    const int tq   = lane & 3;

    const uint32_t sbase = (uint32_t)__cvta_generic_to_shared(sm);

    const int crow[4] = { (t + 0) >> 3, (t + 256) >> 3, (t + 512) >> 3, (t + 768) >> 3 };
    const int ccol    = (t & 7) * 8;

    const int rA = ((lane >> 3) & 1) * 8 + (lane & 7);
    const int cA = (lane >> 4) * 8;
    const int rB = ((lane >> 4) & 1) * 8 + (lane & 7);
    const int cB = ((lane >> 3) & 1) * 8;

    float acc[4][4][4];
#pragma unroll
    for (int a_ = 0; a_ < 4; a_++)
#pragma unroll
        for (int b_ = 0; b_ < 4; b_++)
#pragma unroll
            for (int c_ = 0; c_ < 4; c_++) acc[a_][b_][c_] = 0.f;

    const int KT = kLen >> 6;   // k-tiles of 64

#pragma unroll
    for (int s = 0; s < 2; s++) {
        const int kb = s * 64;
        const uint32_t sb = sbase + s * STAGEB;
#pragma unroll
        for (int i = 0; i < 4; i++) {
            const uint32_t da = sb + (uint32_t)((crow[i] * LDH + ccol) * 2);
            cp16(da,          &A [(size_t)(m0 + crow[i]) * lda + kb + ccol]);
            cp16(da + ABYTES, &BT[(size_t)(n0 + crow[i]) * ldb + kb + ccol]);
        }
        CP_COMMIT();
    }

    for (int kt = 0; kt < KT; kt++) {
        CP_WAIT1();
        __syncthreads();

        const int nkt = kt + 2;
        if (nkt < KT) {
            const int kb = nkt * 64;
            const uint32_t sb = sbase + (nkt % NSTAGE) * STAGEB;
#pragma unroll
            for (int i = 0; i < 4; i++) {
                const uint32_t da = sb + (uint32_t)((crow[i] * LDH + ccol) * 2);
                cp16(da,          &A [(size_t)(m0 + crow[i]) * lda + kb + ccol]);
                cp16(da + ABYTES, &BT[(size_t)(n0 + crow[i]) * ldb + kb + ccol]);
            }
        }
        CP_COMMIT();

        const uint32_t aBuf = sbase + (kt % NSTAGE) * STAGEB;
        const uint32_t bBuf = aBuf + ABYTES;
#pragma unroll
        for (int kq = 0; kq < 4; kq++) {
            uint32_t bf[2][4];
#pragma unroll
            for (int p = 0; p < 2; p++)
                ldsm_x4(bf[p], bBuf + (uint32_t)(((wn * 32 + p * 16 + rB) * LDH + kq * 16 + cB) * 2));
            uint32_t af[4][4];
#pragma unroll
            for (int mt = 0; mt < 4; mt++)
                ldsm_x4(af[mt], aBuf + (uint32_t)(((wm * 64 + mt * 16 + rA) * LDH + kq * 16 + cA) * 2));
#pragma unroll
            for (int mt = 0; mt < 4; mt++)
#pragma unroll
                for (int p = 0; p < 2; p++) {
                    mma_f16(acc[mt][2 * p],     af[mt], &bf[p][0]);
                    mma_f16(acc[mt][2 * p + 1], af[mt], &bf[p][2]);
                }
        }
    }

#pragma unroll
    for (int mt = 0; mt < 4; mt++) {
        const int row = m0 + wm * 64 + mt * 16 + g;
#pragma unroll
        for (int nt = 0; nt < 4; nt++) {
            const int col = n0 + wn * 32 + nt * 8 + tq * 2;
            float bx = 0.f, by = 0.f;
            if (MODE < 2) { float2 bb = *(const float2*)&bias[col]; bx = bb.x; by = bb.y; }
            float v0 = acc[mt][nt][0] + bx;
            float v1 = acc[mt][nt][1] + by;
            float v2 = acc[mt][nt][2] + bx;
            float v3 = acc[mt][nt][3] + by;
            if (MODE == 1) {
                v0 = fmaxf(v0, 0.f); v1 = fmaxf(v1, 0.f);
                v2 = fmaxf(v2, 0.f); v3 = fmaxf(v3, 0.f);
            }
            if constexpr (sizeof(OutT) == 2) {
                *(__half2*)&C[(size_t)row * ldc + col]       = __floats2half2_rn(v0, v1);
                *(__half2*)&C[(size_t)(row + 8) * ldc + col] = __floats2half2_rn(v2, v3);
            } else {
                *(float2*)&C[(size_t)row * ldc + col]       = make_float2(v0, v1);
                *(float2*)&C[(size_t)(row + 8) * ldc + col] = make_float2(v2, v3);
            }
        }
    }
}

template <int MODE, typename OutT>
__global__ __launch_bounds__(256, 2)
void gemm_mma(const __half* __restrict__ A, int lda,
              const __half* __restrict__ BT, int ldb,
              OutT* __restrict__ C, int ldc, size_t cSlice,
              const float* __restrict__ bias, int kLen)
{
    extern __shared__ __align__(16) __half sm[];
    gemm_body<MODE, OutT>(A + (size_t)blockIdx.z * kLen, lda,
                          BT + (size_t)blockIdx.z * kLen, ldb,
                          C + (size_t)blockIdx.z * cSlice, ldc,
                          bias, kLen, sm, blockIdx.y * 128, blockIdx.x * 128);
}

// dual projection: bx 0..1 -> value proj (fp16 out), bx 2..4 -> off+attn (fp32)
__global__ __launch_bounds__(256, 2)
void gemm_dual(const __half* __restrict__ srch, const __half* __restrict__ qh,
               const __half* __restrict__ wvT, const __half* __restrict__ woaT,
               __half* __restrict__ valh, float* __restrict__ offattn,
               const float* __restrict__ b_value, const float* __restrict__ boa)
{
    extern __shared__ __align__(16) __half sm[];
    const int bx = blockIdx.x;
    const int m0 = blockIdx.y * 128;
    if (bx < 2) {
        gemm_body<0, __half>(srch, 256, wvT, 256, valh, 256, b_value, 256,
                             sm, m0, bx * 128);
    } else {
        gemm_body<0, float>(qh, 256, woaT, 256, offattn, 384, boa, 256,
                            sm, m0, (bx - 2) * 128);
    }
}

// ---------------- 128x64 GEMM (R6-proven body), 3 CTAs/SM ---------------
#define LDH6      40
#define ABYTES6   (128 * LDH6 * 2)        // 10240
#define STAGEB6   (ABYTES6 + 64 * LDH6 * 2) // 15360
#define SMBYTES6  (3 * STAGEB6)           // 46080

__global__ __launch_bounds__(256, 3)
void gemm64_bias(const __half* __restrict__ A, int lda,
                 const __half* __restrict__ BT, int ldb,
                 float* __restrict__ C, int ldc,
                 const float* __restrict__ bias, int kLen)
{
    extern __shared__ __align__(16) __half sm6[];
    const uint32_t sbase = (uint32_t)__cvta_generic_to_shared(sm6);

    const int t    = threadIdx.x;
    const int warp = t >> 5;
    const int lane = t & 31;
    const int wm   = warp & 3;
    const int wn   = warp >> 2;
    const int g    = lane >> 2;
    const int tq   = lane & 3;
    const int m0 = blockIdx.y * 128;
    const int n0 = blockIdx.x * 64;

    const int ar0 = t >> 2, ac = (t & 3) * 8;

    const int rA = ((lane >> 3) & 1) * 8 + (lane & 7);
    const int cA = (lane >> 4) * 8;
    const int rB = ((lane >> 4) & 1) * 8 + (lane & 7);
    const int cB = ((lane >> 3) & 1) * 8;

    float acc[2][4][4];
#pragma unroll
    for (int a_ = 0; a_ < 2; a_++)
#pragma unroll
        for (int b_ = 0; b_ < 4; b_++)
#pragma unroll
            for (int c_ = 0; c_ < 4; c_++) acc[a_][b_][c_] = 0.f;

    const int KT = kLen >> 5;

#pragma unroll
    for (int s = 0; s < 2; s++) {
        const int kb = s * 32;
        const uint32_t sb = sbase + s * STAGEB6;
        cp16(sb + (uint32_t)((ar0 * LDH6 + ac) * 2),
             &A[(size_t)(m0 + ar0) * lda + kb + ac]);
        cp16(sb + (uint32_t)(((ar0 + 64) * LDH6 + ac) * 2),
             &A[(size_t)(m0 + ar0 + 64) * lda + kb + ac]);
        cp16(sb + ABYTES6 + (uint32_t)((ar0 * LDH6 + ac) * 2),
             &BT[(size_t)(n0 + ar0) * ldb + kb + ac]);
        CP_COMMIT();
    }

    for (int kt = 0; kt < KT; kt++) {
        CP_WAIT1();
        __syncthreads();

        const int nkt = kt + 2;
        if (nkt < KT) {
            const int kb = nkt * 32;
            const uint32_t sb = sbase + (nkt % 3) * STAGEB6;
            cp16(sb + (uint32_t)((ar0 * LDH6 + ac) * 2),
                 &A[(size_t)(m0 + ar0) * lda + kb + ac]);
            cp16(sb + (uint32_t)(((ar0 + 64) * LDH6 + ac) * 2),
                 &A[(size_t)(m0 + ar0 + 64) * lda + kb + ac]);
            cp16(sb + ABYTES6 + (uint32_t)((ar0 * LDH6 + ac) * 2),
                 &BT[(size_t)(n0 + ar0) * ldb + kb + ac]);
        }
        CP_COMMIT();

        const uint32_t aBuf = sbase + (kt % 3) * STAGEB6;
        const uint32_t bBuf = aBuf + ABYTES6;
#pragma unroll
        for (int kq = 0; kq < 2; kq++) {
            uint32_t af[2][4], bf[2][4];
#pragma unroll
            for (int mt = 0; mt < 2; mt++)
                ldsm_x4(af[mt], aBuf + (uint32_t)(((wm * 32 + mt * 16 + rA) * LDH6 + kq * 16 + cA) * 2));
#pragma unroll
            for (int p = 0; p < 2; p++)
                ldsm_x4(bf[p], bBuf + (uint32_t)(((wn * 32 + p * 16 + rB) * LDH6 + kq * 16 + cB) * 2));
#pragma unroll
            for (int mt = 0; mt < 2; mt++)
#pragma unroll
                for (int p = 0; p < 2; p++) {
                    mma_f16(acc[mt][2 * p],     af[mt], &bf[p][0]);
                    mma_f16(acc[mt][2 * p + 1], af[mt], &bf[p][2]);
                }
        }
    }

#pragma unroll
    for (int mt = 0; mt < 2; mt++) {
        const int row = m0 + wm * 32 + mt * 16 + g;
#pragma unroll
        for (int nt = 0; nt < 4; nt++) {
            const int col = n0 + wn * 32 + nt * 8 + tq * 2;
            float2 bb = *(const float2*)&bias[col];
            *(float2*)&C[(size_t)row * ldc + col] =
                make_float2(acc[mt][nt][0] + bb.x, acc[mt][nt][1] + bb.y);
            *(float2*)&C[(size_t)(row + 8) * ldc + col] =
                make_float2(acc[mt][nt][2] + bb.x, acc[mt][nt][3] + bb.y);
        }
    }
}

// ---------------- deformable sampling: precompute + gather (packed) ------
__global__ __launch_bounds__(256)
void sample_kernel(const __half* __restrict__ value,
                   const float* __restrict__ oa,
                   __half* __restrict__ samp)
{
    __shared__ int2 sWI[8][64];

    const int m    = blockIdx.x;
    const int h    = threadIdx.x >> 5;
    const int lane = threadIdx.x & 31;
    const int b    = m / LEN_TOK;
    const int qi   = m - b * LEN_TOK;

    int Wq, idx;
    if      (qi < 4096) { Wq = 64; idx = qi; }
    else if (qi < 5120) { Wq = 32; idx = qi - 4096; }
    else if (qi < 5376) { Wq = 16; idx = qi - 5120; }
    else                { Wq = 8;  idx = qi - 5376; }
    const int   row = idx / Wq;
    const int   col = idx - row * Wq;
    const float rx  = (col + 0.5f) / (float)Wq;
    const float ry  = (row + 0.5f) / (float)Wq;

    const float offv = oa[(size_t)m * 384 + h * 32 + lane];

    float logit = (lane < 16) ? oa[(size_t)m * 384 + 256 + h * 16 + lane] : -1e30f;
    float mx = logit;
#pragma unroll
    for (int s = 8; s > 0; s >>= 1) mx = fmaxf(mx, __shfl_xor_sync(0xffffffffu, mx, s));
    float e = (lane < 16) ? expf(logit - mx) : 0.0f;
    float sm = e;
#pragma unroll
    for (int s = 8; s > 0; s >>= 1) sm += __shfl_xor_sync(0xffffffffu, sm, s);
    const float prob = e / sm;

    const int pt = lane & 15;
    const float a  = __shfl_sync(0xffffffffu, prob, pt);
    const float ox = __shfl_sync(0xffffffffu, offv, 2 * pt);
    const float oy = __shfl_sync(0xffffffffu, offv, 2 * pt + 1);
    if (lane < 16) {
        const int   l  = pt >> 2;
        const int   Wl = c_lvlW[l];
        const float Wf = (float)Wl;
        const float x = rx * Wf + ox - 0.5f;
        const float y = ry * Wf + oy - 0.5f;
        const float x0f = floorf(x), y0f = floorf(y);
        const float dx = x - x0f, dy = y - y0f;
        const int x0 = (int)x0f, y0 = (int)y0f;
        const int x1 = x0 + 1,   y1 = y0 + 1;
        const float wx0 = ((x0 >= 0) & (x0 < Wl)) ? (1.f - dx) : 0.f;
        const float wx1 = ((x1 >= 0) & (x1 < Wl)) ? dx : 0.f;
        const float wy0 = ((y0 >= 0) & (y0 < Wl)) ? (1.f - dy) : 0.f;
        const float wy1 = ((y1 >= 0) & (y1 < Wl)) ? dy : 0.f;
        const int x0c = min(max(x0, 0), Wl - 1), x1c = min(max(x1, 0), Wl - 1);
        const int y0c = min(max(y0, 0), Wl - 1), y1c = min(max(y1, 0), Wl - 1);
        const int base = c_lvlStart[l];
        sWI[h][pt * 4 + 0] = make_int2(base + y0c * Wl + x0c, __float_as_int(wx0 * wy0 * a));
        sWI[h][pt * 4 + 1] = make_int2(base + y0c * Wl + x1c, __float_as_int(wx1 * wy0 * a));
        sWI[h][pt * 4 + 2] = make_int2(base + y1c * Wl + x0c, __float_as_int(wx0 * wy1 * a));
        sWI[h][pt * 4 + 3] = make_int2(base + y1c * Wl + x1c, __float_as_int(wx1 * wy1 * a));
    }
    __syncwarp();

    const int tap = lane >> 3;
    const int c4  = lane & 7;
    const __half* vb = value + ((size_t)b * LEN_TOK) * 256 + h * 32 + c4 * 4;

    float4 acc = make_float4(0.f, 0.f, 0.f, 0.f);
#pragma unroll
    for (int p = 0; p < 16; p++) {
        const int2  wi = sWI[h][p * 4 + tap];
        const float w  = __int_as_float(wi.y);
        const uint2 raw = *(const uint2*)&vb[(size_t)wi.x * 256];
        const float2 v01 = __half22float2(*(const __half2*)&raw.x);
        const float2 v23 = __half22float2(*(const __half2*)&raw.y);
        acc.x = fmaf(w, v01.x, acc.x);
        acc.y = fmaf(w, v01.y, acc.y);
        acc.z = fmaf(w, v23.x, acc.z);
        acc.w = fmaf(w, v23.y, acc.w);
    }
#pragma unroll
    for (int s = 8; s <= 16; s <<= 1) {
        acc.x += __shfl_xor_sync(0xffffffffu, acc.x, s);
        acc.y += __shfl_xor_sync(0xffffffffu, acc.y, s);
        acc.z += __shfl_xor_sync(0xffffffffu, acc.z, s);
        acc.w += __shfl_xor_sync(0xffffffffu, acc.w, s);
    }
    if (lane < 8) {
        __half* dst = &samp[(size_t)m * 256 + h * 32 + c4 * 4];
        *(__half2*)&dst[0] = __floats2half2_rn(acc.x, acc.y);
        *(__half2*)&dst[2] = __floats2half2_rn(acc.z, acc.w);
    }
}

// ---------------- warp-per-row residual-add + LayerNorm ------------------
// block = 256 thr = 8 warps = 8 rows; lane owns 8 consecutive channels.
__global__ __launch_bounds__(256)
void add_ln_kernel(const float* __restrict__ A, const float* __restrict__ Bv,
                   const float* __restrict__ gamma, const float* __restrict__ beta,
                   float* __restrict__ out, __half* __restrict__ outh)
{
    const int warp = threadIdx.x >> 5;
    const int lane = threadIdx.x & 31;
    const int m = blockIdx.x * 8 + warp;
    const size_t base = (size_t)m * 256 + lane * 8;

    float4 a0 = *(const float4*)&A[base];
    float4 a1 = *(const float4*)&A[base + 4];
    float4 b0 = *(const float4*)&Bv[base];
    float4 b1 = *(const float4*)&Bv[base + 4];
    float v[8] = { a0.x + b0.x, a0.y + b0.y, a0.z + b0.z, a0.w + b0.w,
                   a1.x + b1.x, a1.y + b1.y, a1.z + b1.z, a1.w + b1.w };

    float s = 0.f, q2 = 0.f;
#pragma unroll
    for (int i = 0; i < 8; i++) { s += v[i]; q2 += v[i] * v[i]; }
#pragma unroll
    for (int sft = 16; sft > 0; sft >>= 1) {
        s  += __shfl_xor_sync(0xffffffffu, s,  sft);
        q2 += __shfl_xor_sync(0xffffffffu, q2, sft);
    }
    const float mean = s * (1.0f / 256.0f);
    const float rstd = rsqrtf(q2 * (1.0f / 256.0f) - mean * mean + 1e-5f);

    float4 g0 = *(const float4*)&gamma[lane * 8];
    float4 g1v = *(const float4*)&gamma[lane * 8 + 4];
    float4 be0 = *(const float4*)&beta[lane * 8];
    float4 be1v = *(const float4*)&beta[lane * 8 + 4];
    float gg[8] = { g0.x, g0.y, g0.z, g0.w, g1v.x, g1v.y, g1v.z, g1v.w };
    float bb[8] = { be0.x, be0.y, be0.z, be0.w, be1v.x, be1v.y, be1v.z, be1v.w };

    float o[8];
#pragma unroll
    for (int i = 0; i < 8; i++) o[i] = (v[i] - mean) * rstd * gg[i] + bb[i];

    *(float4*)&out[base]     = make_float4(o[0], o[1], o[2], o[3]);
    *(float4*)&out[base + 4] = make_float4(o[4], o[5], o[6], o[7]);
    __half2 h01 = __floats2half2_rn(o[0], o[1]);
    __half2 h23 = __floats2half2_rn(o[2], o[3]);
    __half2 h45 = __floats2half2_rn(o[4], o[5]);
    __half2 h67 = __floats2half2_rn(o[6], o[7]);
    uint4 hv;
    hv.x = *(uint32_t*)&h01; hv.y = *(uint32_t*)&h23;
    hv.z = *(uint32_t*)&h45; hv.w = *(uint32_t*)&h67;
    *(uint4*)&outh[base] = hv;
}

// ---- warp-per-row: 4 FFN2 partials + b2 + residual + LayerNorm ---------
__global__ __launch_bounds__(256)
void add4_ln_kernel(const float* __restrict__ X, const float* __restrict__ P,
                    const float* __restrict__ bias,
                    const float* __restrict__ gamma, const float* __restrict__ beta,
                    float* __restrict__ out)
{
    const int warp = threadIdx.x >> 5;
    const int lane = threadIdx.x & 31;
    const int m = blockIdx.x * 8 + warp;
    const size_t base = (size_t)m * 256 + lane * 8;
    const size_t sl = (size_t)M_TOK * 256;

    float v[8];
    {
        float4 x0 = *(const float4*)&X[base];
        float4 x1 = *(const float4*)&X[base + 4];
        float4 c0 = *(const float4*)&bias[lane * 8];
        float4 c1 = *(const float4*)&bias[lane * 8 + 4];
        v[0] = x0.x + c0.x; v[1] = x0.y + c0.y; v[2] = x0.z + c0.z; v[3] = x0.w + c0.w;
        v[4] = x1.x + c1.x; v[5] = x1.y + c1.y; v[6] = x1.z + c1.z; v[7] = x1.w + c1.w;
    }
#pragma unroll
    for (int sp = 0; sp < 4; sp++) {
        float4 p0 = *(const float4*)&P[base + sp * sl];
        float4 p1 = *(const float4*)&P[base + sp * sl + 4];
        v[0] += p0.x; v[1] += p0.y; v[2] += p0.z; v[3] += p0.w;
        v[4] += p1.x; v[5] += p1.y; v[6] += p1.z; v[7] += p1.w;
    }

    float s = 0.f, q2 = 0.f;
#pragma unroll
    for (int i = 0; i < 8; i++) { s += v[i]; q2 += v[i] * v[i]; }
#pragma unroll
    for (int sft = 16; sft > 0; sft >>= 1) {
        s  += __shfl_xor_sync(0xffffffffu, s,  sft);
        q2 += __shfl_xor_sync(0xffffffffu, q2, sft);
    }
    const float mean = s * (1.0f / 256.0f);
    const float rstd = rsqrtf(q2 * (1.0f / 256.0f) - mean * mean + 1e-5f);

    float4 g0 = *(const float4*)&gamma[lane * 8];
    float4 g1v = *(const float4*)&gamma[lane * 8 + 4];
    float4 be0 = *(const float4*)&beta[lane * 8];
    float4 be1v = *(const float4*)&beta[lane * 8 + 4];
    float gg[8] = { g0.x, g0.y, g0.z, g0.w, g1v.x, g1v.y, g1v.z, g1v.w };
    float bb[8] = { be0.x, be0.y, be0.z, be0.w, be1v.x, be1v.y, be1v.z, be1v.w };

    float o[8];
#pragma unroll
    for (int i = 0; i < 8; i++) o[i] = (v[i] - mean) * rstd * gg[i] + bb[i];

    *(float4*)&out[base]     = make_float4(o[0], o[1], o[2], o[3]);
    *(float4*)&out[base + 4] = make_float4(o[4], o[5], o[6], o[7]);
}

// ---------------- launch -------------------------------------------------
template <typename T>
static inline T* sym(const void* s)
{
    void* p = nullptr;
    cudaGetSymbolAddress(&p, s);
    return (T*)p;
}

extern "C" void kernel_launch(void* const* d_in, const int* in_sizes, int n_in,
                              void* d_out, int out_size)
{
    const float* src     = (const float*)d_in[0];
    const float* pos     = (const float*)d_in[1];
    const float* w_value = (const float*)d_in[4];
    const float* b_value = (const float*)d_in[5];
    const float* w_off   = (const float*)d_in[6];
    const float* b_off   = (const float*)d_in[7];
    const float* w_attn  = (const float*)d_in[8];
    const float* b_attn  = (const float*)d_in[9];
    const float* w_out   = (const float*)d_in[10];
    const float* b_out   = (const float*)d_in[11];
    const float* w1      = (const float*)d_in[12];
    const float* b1      = (const float*)d_in[13];
    const float* w2      = (const float*)d_in[14];
    const float* b2      = (const float*)d_in[15];
    const float* g1      = (const float*)d_in[16];
    const float* be1     = (const float*)d_in[17];
    const float* g2      = (const float*)d_in[18];
    const float* be2     = (const float*)d_in[19];
    float* out = (float*)d_out;

    __half* valh    = sym<__half>(g_valh);
    float*  offattn = sym<float>(g_offattn);
    float*  out2    = sym<float>(g_out2);
    float*  x       = sym<float>(g_x);
    float*  part    = sym<float>(g_part);
    float*  boa     = sym<float>(g_boa);
    __half* srch    = sym<__half>(g_srch);
    __half* qh      = sym<__half>(g_qh);
    __half* samph   = sym<__half>(g_samph);
    __half* xh      = sym<__half>(g_xh);
    __half* ffhh    = sym<__half>(g_ffhh);
    __half* wvT     = sym<__half>(g_wvT);
    __half* woaT    = sym<__half>(g_woaT);
    __half* woutT   = sym<__half>(g_woutT);
    __half* w1T     = sym<__half>(g_w1T);
    __half* w2T     = sym<__half>(g_w2T);

    cudaFuncSetAttribute(gemm_mma<1, __half>, cudaFuncAttributeMaxDynamicSharedMemorySize, SMBYTES);
    cudaFuncSetAttribute(gemm_mma<2, float>,  cudaFuncAttributeMaxDynamicSharedMemorySize, SMBYTES);
    cudaFuncSetAttribute(gemm_dual,           cudaFuncAttributeMaxDynamicSharedMemorySize, SMBYTES);

    // prep: addcvt (2720) + transposes (1248) + bias concat (1)
    prep_kernel<<<PREP_BLKS, 256>>>((const float4*)src, (const float4*)pos,
                                    (__half2*)qh, (__half2*)srch,
                                    w_value, w_off, w_attn, w_out, w1, w2,
                                    wvT, woaT, woutT, w1T, w2T,
                                    b_off, b_attn, boa);

    // value proj (fp16 out) + off/attn proj (fp32 out), one launch
    gemm_dual<<<dim3(5, M_TOK / 128), 256, SMBYTES>>>(srch, qh, wvT, woaT,
                                                      valh, offattn, b_value, boa);

    // deformable sampling (softmax fused, precompute+gather)
    sample_kernel<<<M_TOK, 256>>>(valh, offattn, samph);

    // output projection: 128x64 tiles, 3 CTAs/SM
    gemm64_bias<<<dim3(4, M_TOK / 128), 256, SMBYTES6>>>(
        samph, 256, woutT, 256, out2, 256, b_out, 256);

    // x = LN(src + out2), warp-per-row
    add_ln_kernel<<<M_TOK / 8, 256>>>(src, out2, g1, be1, x, xh);

    // FFN1: relu(x @ w1 + b1), fp16 out
    gemm_mma<1, __half><<<dim3(16, M_TOK / 128), 256, SMBYTES>>>(
        xh, 256, w1T, 256, ffhh, DFF, 0, b1, 256);

    // FFN2: split-K=4 partials (kLen=512 each)
    gemm_mma<2, float><<<dim3(2, M_TOK / 128, 4), 256, SMBYTES>>>(
        ffhh, DFF, w2T, DFF, part, 256, (size_t)M_TOK * 256, nullptr, 512);

    // out = LN(x + sum(parts) + b2), warp-per-row
    add4_ln_kernel<<<M_TOK / 8, 256>>>(x, part, b2, g2, be2, out);
}

// round 17
// speedup vs baseline: 1.0901x; 1.0025x over previous
#include <cuda_runtime.h>
#include <cuda_fp16.h>
#include <cstdint>
#include <math.h>

// ---------------- problem constants (fixed by dataset) ----------------
#define B_BATCH   2
#define LEN_TOK   5440
#define M_TOK     (B_BATCH * LEN_TOK)   // 10880
#define DMODEL    256
#define NHEAD     8
#define NLVL      4
#define NPT       4
#define DFF       2048

__device__ __constant__ int c_lvlW[4]     = {64, 32, 16, 8};
__device__ __constant__ int c_lvlStart[4] = {0, 4096, 5120, 5376};

// ---------------- scratch (static device globals; no allocation) ------
__device__ __half g_valh[M_TOK * DMODEL];
__device__ float  g_offattn[M_TOK * 384];
__device__ __half g_out2[M_TOK * DMODEL];
__device__ float  g_x   [M_TOK * DMODEL];
__device__ __half g_part[4 * M_TOK * DMODEL];
__device__ __half g_srch[M_TOK * DMODEL];
__device__ __half g_qh  [M_TOK * DMODEL];
__device__ __half g_samph[M_TOK * DMODEL];
__device__ __half g_xh  [M_TOK * DMODEL];
__device__ __half g_ffhh[M_TOK * DFF];
__device__ float  g_boa [384];
__device__ __half g_wvT  [256 * 256];
__device__ __half g_woaT [384 * 256];
__device__ __half g_woutT[256 * 256];
__device__ __half g_w1T  [2048 * 256];
__device__ __half g_w2T  [256 * 2048];

// ---------------- mma / ldmatrix / cp.async helpers ----------------------
__device__ __forceinline__ void mma_f16(float* c, const uint32_t* a, const uint32_t* b) {
    asm volatile(
        "mma.sync.aligned.m16n8k16.row.col.f32.f16.f16.f32 "
        "{%0,%1,%2,%3}, {%4,%5,%6,%7}, {%8,%9}, {%0,%1,%2,%3};\n"
        : "+f"(c[0]), "+f"(c[1]), "+f"(c[2]), "+f"(c[3])
        : "r"(a[0]), "r"(a[1]), "r"(a[2]), "r"(a[3]), "r"(b[0]), "r"(b[1]));
}
__device__ __forceinline__ void ldsm_x4(uint32_t* r, uint32_t addr) {
    asm volatile("ldmatrix.sync.aligned.m8n8.x4.shared.b16 {%0,%1,%2,%3}, [%4];"
                 : "=r"(r[0]), "=r"(r[1]), "=r"(r[2]), "=r"(r[3]) : "r"(addr));
}
__device__ __forceinline__ void cp16(uint32_t saddr, const void* g) {
    asm volatile("cp.async.cg.shared.global [%0], [%1], 16;" :: "r"(saddr), "l"(g));
}
#define CP_COMMIT() asm volatile("cp.async.commit_group;" ::: "memory")
#define CP_WAIT1()  asm volatile("cp.async.wait_group 1;" ::: "memory")

// ---------------- prep: addcvt + all transposes + bias concat ------------
#define PREP_CVT_BLKS  2720
#define PREP_TR_BASE   PREP_CVT_BLKS
#define PREP_BIAS_BLK  (PREP_TR_BASE + 1248)
#define PREP_BLKS      (PREP_BIAS_BLK + 1)

__global__ __launch_bounds__(256)
void prep_kernel(const float4* __restrict__ src4, const float4* __restrict__ pos4,
                 __half2* __restrict__ qh, __half2* __restrict__ srch,
                 const float* __restrict__ wv, const float* __restrict__ woff,
                 const float* __restrict__ wattn, const float* __restrict__ wout,
                 const float* __restrict__ w1, const float* __restrict__ w2,
                 __half* __restrict__ wvT, __half* __restrict__ woaT,
                 __half* __restrict__ woutT,
                 __half* __restrict__ w1T, __half* __restrict__ w2T,
                 const float* __restrict__ b_off, const float* __restrict__ b_attn,
                 float* __restrict__ boa)
{
    const int bid = blockIdx.x;
    const int t = threadIdx.x;

    if (bid < PREP_CVT_BLKS) {
        const int i = bid * 256 + t;
        float4 s = src4[i], p = pos4[i];
        srch[2 * i]     = __floats2half2_rn(s.x, s.y);
        srch[2 * i + 1] = __floats2half2_rn(s.z, s.w);
        qh[2 * i]       = __floats2half2_rn(s.x + p.x, s.y + p.y);
        qh[2 * i + 1]   = __floats2half2_rn(s.z + p.z, s.w + p.w);
        return;
    }
    if (bid == PREP_BIAS_BLK) {
        if (t < 256) boa[t] = b_off[t];
        if (t < 128) boa[256 + t] = b_attn[t];
        return;
    }
    const int tb = bid - PREP_TR_BASE;
    const float* in; __half* out; int R, C, tix;
    if      (tb < 64)  { in = wv;    out = wvT;            R = 256;  C = 256;  tix = tb; }
    else if (tb < 128) { in = woff;  out = woaT;           R = 256;  C = 256;  tix = tb - 64; }
    else if (tb < 160) { in = wattn; out = woaT + 256*256; R = 256;  C = 128;  tix = tb - 128; }
    else if (tb < 224) { in = wout;  out = woutT;          R = 256;  C = 256;  tix = tb - 160; }
    else if (tb < 736) { in = w1;    out = w1T;            R = 256;  C = 2048; tix = tb - 224; }
    else               { in = w2;    out = w2T;            R = 2048; C = 256;  tix = tb - 736; }
    const int tilesX = C / 32;
    const int c0 = (tix % tilesX) * 32, r0 = (tix / tilesX) * 32;

    __shared__ float tile[32][33];
    const int x = t & 31, y = t >> 5;
#pragma unroll
    for (int i = 0; i < 32; i += 8)
        tile[y + i][x] = in[(size_t)(r0 + y + i) * C + c0 + x];
    __syncthreads();
#pragma unroll
    for (int i = 0; i < 32; i += 8)
        out[(size_t)(c0 + y + i) * R + r0 + x] = __float2half_rn(tile[x][y + i]);
}

// ---------------- fp16 mma.sync GEMM body: BK=64, 3-stage (proven) -------
#define LDH      72
#define OP_HALVES (128 * LDH)
#define ABYTES   (OP_HALVES * 2)         // 18432
#define STAGEB   (2 * ABYTES)            // 36864
#define NSTAGE   3
#define SMBYTES  (NSTAGE * STAGEB)       // 110592

template <int MODE, typename OutT>
__device__ __forceinline__
void gemm_body(const __half* __restrict__ A, int lda,
               const __half* __restrict__ BT, int ldb,
               OutT* __restrict__ C, int ldc,
               const float* __restrict__ bias, int kLen,
               __half* sm, int m0, int n0)
{
    const int t    = threadIdx.x;
    const int warp = t >> 5;
    const int lane = t & 31;
    const int wm   = warp >> 2;
    const int wn   = warp & 3;
    const int g    = lane >> 2;
    const int tq   = lane & 3;

    const uint32_t sbase = (uint32_t)__cvta_generic_to_shared(sm);

    const int crow[4] = { (t + 0) >> 3, (t + 256) >> 3, (t + 512) >> 3, (t + 768) >> 3 };
    const int ccol    = (t & 7) * 8;

    const int rA = ((lane >> 3) & 1) * 8 + (lane & 7);
    const int cA = (lane >> 4) * 8;
    const int rB = ((lane >> 4) & 1) * 8 + (lane & 7);
    const int cB = ((lane >> 3) & 1) * 8;

    float acc[4][4][4];
#pragma unroll
    for (int a_ = 0; a_ < 4; a_++)
#pragma unroll
        for (int b_ = 0; b_ < 4; b_++)
#pragma unroll
            for (int c_ = 0; c_ < 4; c_++) acc[a_][b_][c_] = 0.f;

    const int KT = kLen >> 6;   // k-tiles of 64

#pragma unroll
    for (int s = 0; s < 2; s++) {
        const int kb = s * 64;
        const uint32_t sb = sbase + s * STAGEB;
#pragma unroll
        for (int i = 0; i < 4; i++) {
            const uint32_t da = sb + (uint32_t)((crow[i] * LDH + ccol) * 2);
            cp16(da,          &A [(size_t)(m0 + crow[i]) * lda + kb + ccol]);
            cp16(da + ABYTES, &BT[(size_t)(n0 + crow[i]) * ldb + kb + ccol]);
        }
        CP_COMMIT();
    }

    for (int kt = 0; kt < KT; kt++) {
        CP_WAIT1();
        __syncthreads();

        const int nkt = kt + 2;
        if (nkt < KT) {
            const int kb = nkt * 64;
            const uint32_t sb = sbase + (nkt % NSTAGE) * STAGEB;
#pragma unroll
            for (int i = 0; i < 4; i++) {
                const uint32_t da = sb + (uint32_t)((crow[i] * LDH + ccol) * 2);
                cp16(da,          &A [(size_t)(m0 + crow[i]) * lda + kb + ccol]);
                cp16(da + ABYTES, &BT[(size_t)(n0 + crow[i]) * ldb + kb + ccol]);
            }
        }
        CP_COMMIT();

        const uint32_t aBuf = sbase + (kt % NSTAGE) * STAGEB;
        const uint32_t bBuf = aBuf + ABYTES;
#pragma unroll
        for (int kq = 0; kq < 4; kq++) {
            uint32_t bf[2][4];
#pragma unroll
            for (int p = 0; p < 2; p++)
                ldsm_x4(bf[p], bBuf + (uint32_t)(((wn * 32 + p * 16 + rB) * LDH + kq * 16 + cB) * 2));
            uint32_t af[4][4];
#pragma unroll
            for (int mt = 0; mt < 4; mt++)
                ldsm_x4(af[mt], aBuf + (uint32_t)(((wm * 64 + mt * 16 + rA) * LDH + kq * 16 + cA) * 2));
#pragma unroll
            for (int mt = 0; mt < 4; mt++)
#pragma unroll
                for (int p = 0; p < 2; p++) {
                    mma_f16(acc[mt][2 * p],     af[mt], &bf[p][0]);
                    mma_f16(acc[mt][2 * p + 1], af[mt], &bf[p][2]);
                }
        }
    }

#pragma unroll
    for (int mt = 0; mt < 4; mt++) {
        const int row = m0 + wm * 64 + mt * 16 + g;
#pragma unroll
        for (int nt = 0; nt < 4; nt++) {
            const int col = n0 + wn * 32 + nt * 8 + tq * 2;
            float bx = 0.f, by = 0.f;
            if (MODE < 2) { float2 bb = *(const float2*)&bias[col]; bx = bb.x; by = bb.y; }
            float v0 = acc[mt][nt][0] + bx;
            float v1 = acc[mt][nt][1] + by;
            float v2 = acc[mt][nt][2] + bx;
            float v3 = acc[mt][nt][3] + by;
            if (MODE == 1) {
                v0 = fmaxf(v0, 0.f); v1 = fmaxf(v1, 0.f);
                v2 = fmaxf(v2, 0.f); v3 = fmaxf(v3, 0.f);
            }
            if constexpr (sizeof(OutT) == 2) {
                *(__half2*)&C[(size_t)row * ldc + col]       = __floats2half2_rn(v0, v1);
                *(__half2*)&C[(size_t)(row + 8) * ldc + col] = __floats2half2_rn(v2, v3);
            } else {
                *(float2*)&C[(size_t)row * ldc + col]       = make_float2(v0, v1);
                *(float2*)&C[(size_t)(row + 8) * ldc + col] = make_float2(v2, v3);
            }
        }
    }
}

template <int MODE, typename OutT>
__global__ __launch_bounds__(256, 2)
void gemm_mma(const __half* __restrict__ A, int lda,
              const __half* __restrict__ BT, int ldb,
              OutT* __restrict__ C, int ldc, size_t cSlice,
              const float* __restrict__ bias, int kLen)
{
    extern __shared__ __align__(16) __half sm[];
    gemm_body<MODE, OutT>(A + (size_t)blockIdx.z * kLen, lda,
                          BT + (size_t)blockIdx.z * kLen, ldb,
                          C + (size_t)blockIdx.z * cSlice, ldc,
                          bias, kLen, sm, blockIdx.y * 128, blockIdx.x * 128);
}

// dual projection: bx 0..1 -> value proj (fp16 out), bx 2..4 -> off+attn (fp32)
__global__ __launch_bounds__(256, 2)
void gemm_dual(const __half* __restrict__ srch, const __half* __restrict__ qh,
               const __half* __restrict__ wvT, const __half* __restrict__ woaT,
               __half* __restrict__ valh, float* __restrict__ offattn,
               const float* __restrict__ b_value, const float* __restrict__ boa)
{
    extern __shared__ __align__(16) __half sm[];
    const int bx = blockIdx.x;
    const int m0 = blockIdx.y * 128;
    if (bx < 2) {
        gemm_body<0, __half>(srch, 256, wvT, 256, valh, 256, b_value, 256,
                             sm, m0, bx * 128);
    } else {
        gemm_body<0, float>(qh, 256, woaT, 256, offattn, 384, boa, 256,
                            sm, m0, (bx - 2) * 128);
    }
}

// ---------------- 128x64 GEMM (proven body), 3 CTAs/SM, fp16 out --------
#define LDH6      40
#define ABYTES6   (128 * LDH6 * 2)        // 10240
#define STAGEB6   (ABYTES6 + 64 * LDH6 * 2) // 15360
#define SMBYTES6  (3 * STAGEB6)           // 46080

__global__ __launch_bounds__(256, 3)
void gemm64_bias(const __half* __restrict__ A, int lda,
                 const __half* __restrict__ BT, int ldb,
                 __half* __restrict__ C, int ldc,
                 const float* __restrict__ bias, int kLen)
{
    extern __shared__ __align__(16) __half sm6[];
    const uint32_t sbase = (uint32_t)__cvta_generic_to_shared(sm6);

    const int t    = threadIdx.x;
    const int warp = t >> 5;
    const int lane = t & 31;
    const int wm   = warp & 3;
    const int wn   = warp >> 2;
    const int g    = lane >> 2;
    const int tq   = lane & 3;
    const int m0 = blockIdx.y * 128;
    const int n0 = blockIdx.x * 64;

    const int ar0 = t >> 2, ac = (t & 3) * 8;

    const int rA = ((lane >> 3) & 1) * 8 + (lane & 7);
    const int cA = (lane >> 4) * 8;
    const int rB = ((lane >> 4) & 1) * 8 + (lane & 7);
    const int cB = ((lane >> 3) & 1) * 8;

    float acc[2][4][4];
#pragma unroll
    for (int a_ = 0; a_ < 2; a_++)
#pragma unroll
        for (int b_ = 0; b_ < 4; b_++)
#pragma unroll
            for (int c_ = 0; c_ < 4; c_++) acc[a_][b_][c_] = 0.f;

    const int KT = kLen >> 5;

#pragma unroll
    for (int s = 0; s < 2; s++) {
        const int kb = s * 32;
        const uint32_t sb = sbase + s * STAGEB6;
        cp16(sb + (uint32_t)((ar0 * LDH6 + ac) * 2),
             &A[(size_t)(m0 + ar0) * lda + kb + ac]);
        cp16(sb + (uint32_t)(((ar0 + 64) * LDH6 + ac) * 2),
             &A[(size_t)(m0 + ar0 + 64) * lda + kb + ac]);
        cp16(sb + ABYTES6 + (uint32_t)((ar0 * LDH6 + ac) * 2),
             &BT[(size_t)(n0 + ar0) * ldb + kb + ac]);
        CP_COMMIT();
    }

    for (int kt = 0; kt < KT; kt++) {
        CP_WAIT1();
        __syncthreads();

        const int nkt = kt + 2;
        if (nkt < KT) {
            const int kb = nkt * 32;
            const uint32_t sb = sbase + (nkt % 3) * STAGEB6;
            cp16(sb + (uint32_t)((ar0 * LDH6 + ac) * 2),
                 &A[(size_t)(m0 + ar0) * lda + kb + ac]);
            cp16(sb + (uint32_t)(((ar0 + 64) * LDH6 + ac) * 2),
                 &A[(size_t)(m0 + ar0 + 64) * lda + kb + ac]);
            cp16(sb + ABYTES6 + (uint32_t)((ar0 * LDH6 + ac) * 2),
                 &BT[(size_t)(n0 + ar0) * ldb + kb + ac]);
        }
        CP_COMMIT();

        const uint32_t aBuf = sbase + (kt % 3) * STAGEB6;
        const uint32_t bBuf = aBuf + ABYTES6;
#pragma unroll
        for (int kq = 0; kq < 2; kq++) {
            uint32_t af[2][4], bf[2][4];
#pragma unroll
            for (int mt = 0; mt < 2; mt++)
                ldsm_x4(af[mt], aBuf + (uint32_t)(((wm * 32 + mt * 16 + rA) * LDH6 + kq * 16 + cA) * 2));
#pragma unroll
            for (int p = 0; p < 2; p++)
                ldsm_x4(bf[p], bBuf + (uint32_t)(((wn * 32 + p * 16 + rB) * LDH6 + kq * 16 + cB) * 2));
#pragma unroll
            for (int mt = 0; mt < 2; mt++)
#pragma unroll
                for (int p = 0; p < 2; p++) {
                    mma_f16(acc[mt][2 * p],     af[mt], &bf[p][0]);
                    mma_f16(acc[mt][2 * p + 1], af[mt], &bf[p][2]);
                }
        }
    }

#pragma unroll
    for (int mt = 0; mt < 2; mt++) {
        const int row = m0 + wm * 32 + mt * 16 + g;
#pragma unroll
        for (int nt = 0; nt < 4; nt++) {
            const int col = n0 + wn * 32 + nt * 8 + tq * 2;
            float2 bb = *(const float2*)&bias[col];
            *(__half2*)&C[(size_t)row * ldc + col] =
                __floats2half2_rn(acc[mt][nt][0] + bb.x, acc[mt][nt][1] + bb.y);
            *(__half2*)&C[(size_t)(row + 8) * ldc + col] =
                __floats2half2_rn(acc[mt][nt][2] + bb.x, acc[mt][nt][3] + bb.y);
        }
    }
}

// ---------------- deformable sampling: precompute + gather (packed) ------
// phase-1 stores pre-scaled BYTE offsets (tok*512) to kill per-iter IMAD.
__global__ __launch_bounds__(256)
void sample_kernel(const __half* __restrict__ value,
                   const float* __restrict__ oa,
                   __half* __restrict__ samp)
{
    __shared__ int2 sWI[8][64];   // {byte offset, w bits}

    const int m    = blockIdx.x;
    const int h    = threadIdx.x >> 5;
    const int lane = threadIdx.x & 31;
    const int b    = m / LEN_TOK;
    const int qi   = m - b * LEN_TOK;

    int Wq, idx;
    if      (qi < 4096) { Wq = 64; idx = qi; }
    else if (qi < 5120) { Wq = 32; idx = qi - 4096; }
    else if (qi < 5376) { Wq = 16; idx = qi - 5120; }
    else                { Wq = 8;  idx = qi - 5376; }
    const int   row = idx / Wq;
    const int   col = idx - row * Wq;
    const float rx  = (col + 0.5f) / (float)Wq;
    const float ry  = (row + 0.5f) / (float)Wq;

    const float offv = oa[(size_t)m * 384 + h * 32 + lane];

    float logit = (lane < 16) ? oa[(size_t)m * 384 + 256 + h * 16 + lane] : -1e30f;
    float mx = logit;
#pragma unroll
    for (int s = 8; s > 0; s >>= 1) mx = fmaxf(mx, __shfl_xor_sync(0xffffffffu, mx, s));
    float e = (lane < 16) ? expf(logit - mx) : 0.0f;
    float sm = e;
#pragma unroll
    for (int s = 8; s > 0; s >>= 1) sm += __shfl_xor_sync(0xffffffffu, sm, s);
    const float prob = e / sm;

    const int pt = lane & 15;
    const float a  = __shfl_sync(0xffffffffu, prob, pt);
    const float ox = __shfl_sync(0xffffffffu, offv, 2 * pt);
    const float oy = __shfl_sync(0xffffffffu, offv, 2 * pt + 1);
    if (lane < 16) {
        const int   l  = pt >> 2;
        const int   Wl = c_lvlW[l];
        const float Wf = (float)Wl;
        const float x = rx * Wf + ox - 0.5f;
        const float y = ry * Wf + oy - 0.5f;
        const float x0f = floorf(x), y0f = floorf(y);
        const float dx = x - x0f, dy = y - y0f;
        const int x0 = (int)x0f, y0 = (int)y0f;
        const int x1 = x0 + 1,   y1 = y0 + 1;
        const float wx0 = ((x0 >= 0) & (x0 < Wl)) ? (1.f - dx) : 0.f;
        const float wx1 = ((x1 >= 0) & (x1 < Wl)) ? dx : 0.f;
        const float wy0 = ((y0 >= 0) & (y0 < Wl)) ? (1.f - dy) : 0.f;
        const float wy1 = ((y1 >= 0) & (y1 < Wl)) ? dy : 0.f;
        const int x0c = min(max(x0, 0), Wl - 1), x1c = min(max(x1, 0), Wl - 1);
        const int y0c = min(max(y0, 0), Wl - 1), y1c = min(max(y1, 0), Wl - 1);
        const int base = c_lvlStart[l];
        sWI[h][pt * 4 + 0] = make_int2((base + y0c * Wl + x0c) * 512, __float_as_int(wx0 * wy0 * a));
        sWI[h][pt * 4 + 1] = make_int2((base + y0c * Wl + x1c) * 512, __float_as_int(wx1 * wy0 * a));
        sWI[h][pt * 4 + 2] = make_int2((base + y1c * Wl + x0c) * 512, __float_as_int(wx0 * wy1 * a));
        sWI[h][pt * 4 + 3] = make_int2((base + y1c * Wl + x1c) * 512, __float_as_int(wx1 * wy1 * a));
    }
    __syncwarp();

    const int tap = lane >> 3;
    const int c4  = lane & 7;
    const char* vb = (const char*)(value + ((size_t)b * LEN_TOK) * 256 + h * 32 + c4 * 4);

    float4 acc = make_float4(0.f, 0.f, 0.f, 0.f);
#pragma unroll
    for (int p = 0; p < 16; p++) {
        const int2  wi = sWI[h][p * 4 + tap];
        const float w  = __int_as_float(wi.y);
        const uint2 raw = *(const uint2*)(vb + wi.x);
        const float2 v01 = __half22float2(*(const __half2*)&raw.x);
        const float2 v23 = __half22float2(*(const __half2*)&raw.y);
        acc.x = fmaf(w, v01.x, acc.x);
        acc.y = fmaf(w, v01.y, acc.y);
        acc.z = fmaf(w, v23.x, acc.z);
        acc.w = fmaf(w, v23.y, acc.w);
    }
#pragma unroll
    for (int s = 8; s <= 16; s <<= 1) {
        acc.x += __shfl_xor_sync(0xffffffffu, acc.x, s);
        acc.y += __shfl_xor_sync(0xffffffffu, acc.y, s);
        acc.z += __shfl_xor_sync(0xffffffffu, acc.z, s);
        acc.w += __shfl_xor_sync(0xffffffffu, acc.w, s);
    }
    if (lane < 8) {
        __half* dst = &samp[(size_t)m * 256 + h * 32 + c4 * 4];
        *(__half2*)&dst[0] = __floats2half2_rn(acc.x, acc.y);
        *(__half2*)&dst[2] = __floats2half2_rn(acc.z, acc.w);
    }
}

// ---------------- warp-per-row residual-add + LayerNorm (fp16 residual) --
__global__ __launch_bounds__(256)
void add_ln_kernel(const float* __restrict__ A, const __half* __restrict__ Bv,
                   const float* __restrict__ gamma, const float* __restrict__ beta,
                   float* __restrict__ out, __half* __restrict__ outh)
{
    const int warp = threadIdx.x >> 5;
    const int lane = threadIdx.x & 31;
    const int m = blockIdx.x * 8 + warp;
    const size_t base = (size_t)m * 256 + lane * 8;

    float4 a0 = *(const float4*)&A[base];
    float4 a1 = *(const float4*)&A[base + 4];
    uint4 bh = *(const uint4*)&Bv[base];
    float2 b01 = __half22float2(*(const __half2*)&bh.x);
    float2 b23 = __half22float2(*(const __half2*)&bh.y);
    float2 b45 = __half22float2(*(const __half2*)&bh.z);
    float2 b67 = __half22float2(*(const __half2*)&bh.w);
    float v[8] = { a0.x + b01.x, a0.y + b01.y, a0.z + b23.x, a0.w + b23.y,
                   a1.x + b45.x, a1.y + b45.y, a1.z + b67.x, a1.w + b67.y };

    float s = 0.f, q2 = 0.f;
#pragma unroll
    for (int i = 0; i < 8; i++) { s += v[i]; q2 += v[i] * v[i]; }
#pragma unroll
    for (int sft = 16; sft > 0; sft >>= 1) {
        s  += __shfl_xor_sync(0xffffffffu, s,  sft);
        q2 += __shfl_xor_sync(0xffffffffu, q2, sft);
    }
    const float mean = s * (1.0f / 256.0f);
    const float rstd = rsqrtf(q2 * (1.0f / 256.0f) - mean * mean + 1e-5f);

    float4 g0 = *(const float4*)&gamma[lane * 8];
    float4 g1v = *(const float4*)&gamma[lane * 8 + 4];
    float4 be0 = *(const float4*)&beta[lane * 8];
    float4 be1v = *(const float4*)&beta[lane * 8 + 4];
    float gg[8] = { g0.x, g0.y, g0.z, g0.w, g1v.x, g1v.y, g1v.z, g1v.w };
    float bb[8] = { be0.x, be0.y, be0.z, be0.w, be1v.x, be1v.y, be1v.z, be1v.w };

    float o[8];
#pragma unroll
    for (int i = 0; i < 8; i++) o[i] = (v[i] - mean) * rstd * gg[i] + bb[i];

    *(float4*)&out[base]     = make_float4(o[0], o[1], o[2], o[3]);
    *(float4*)&out[base + 4] = make_float4(o[4], o[5], o[6], o[7]);
    __half2 h01 = __floats2half2_rn(o[0], o[1]);
    __half2 h23 = __floats2half2_rn(o[2], o[3]);
    __half2 h45 = __floats2half2_rn(o[4], o[5]);
    __half2 h67 = __floats2half2_rn(o[6], o[7]);
    uint4 hv;
    hv.x = *(uint32_t*)&h01; hv.y = *(uint32_t*)&h23;
    hv.z = *(uint32_t*)&h45; hv.w = *(uint32_t*)&h67;
    *(uint4*)&outh[base] = hv;
}

// ---- warp-per-row: 4 fp16 FFN2 partials + b2 + residual + LayerNorm ----
__global__ __launch_bounds__(256)
void add4_ln_kernel(const float* __restrict__ X, const __half* __restrict__ P,
                    const float* __restrict__ bias,
                    const float* __restrict__ gamma, const float* __restrict__ beta,
                    float* __restrict__ out)
{
    const int warp = threadIdx.x >> 5;
    const int lane = threadIdx.x & 31;
    const int m = blockIdx.x * 8 + warp;
    const size_t base = (size_t)m * 256 + lane * 8;
    const size_t sl = (size_t)M_TOK * 256;

    float v[8];
    {
        float4 x0 = *(const float4*)&X[base];
        float4 x1 = *(const float4*)&X[base + 4];
        float4 c0 = *(const float4*)&bias[lane * 8];
        float4 c1 = *(const float4*)&bias[lane * 8 + 4];
        v[0] = x0.x + c0.x; v[1] = x0.y + c0.y; v[2] = x0.z + c0.z; v[3] = x0.w + c0.w;
        v[4] = x1.x + c1.x; v[5] = x1.y + c1.y; v[6] = x1.z + c1.z; v[7] = x1.w + c1.w;
    }
#pragma unroll
    for (int sp = 0; sp < 4; sp++) {
        uint4 ph = *(const uint4*)&P[base + sp * sl];
        float2 p01 = __half22float2(*(const __half2*)&ph.x);
        float2 p23 = __half22float2(*(const __half2*)&ph.y);
        float2 p45 = __half22float2(*(const __half2*)&ph.z);
        float2 p67 = __half22float2(*(const __half2*)&ph.w);
        v[0] += p01.x; v[1] += p01.y; v[2] += p23.x; v[3] += p23.y;
        v[4] += p45.x; v[5] += p45.y; v[6] += p67.x; v[7] += p67.y;
    }

    float s = 0.f, q2 = 0.f;
#pragma unroll
    for (int i = 0; i < 8; i++) { s += v[i]; q2 += v[i] * v[i]; }
#pragma unroll
    for (int sft = 16; sft > 0; sft >>= 1) {
        s  += __shfl_xor_sync(0xffffffffu, s,  sft);
        q2 += __shfl_xor_sync(0xffffffffu, q2, sft);
    }
    const float mean = s * (1.0f / 256.0f);
    const float rstd = rsqrtf(q2 * (1.0f / 256.0f) - mean * mean + 1e-5f);

    float4 g0 = *(const float4*)&gamma[lane * 8];
    float4 g1v = *(const float4*)&gamma[lane * 8 + 4];
    float4 be0 = *(const float4*)&beta[lane * 8];
    float4 be1v = *(const float4*)&beta[lane * 8 + 4];
    float gg[8] = { g0.x, g0.y, g0.z, g0.w, g1v.x, g1v.y, g1v.z, g1v.w };
    float bb[8] = { be0.x, be0.y, be0.z, be0.w, be1v.x, be1v.y, be1v.z, be1v.w };

    float o[8];
#pragma unroll
    for (int i = 0; i < 8; i++) o[i] = (v[i] - mean) * rstd * gg[i] + bb[i];

    *(float4*)&out[base]     = make_float4(o[0], o[1], o[2], o[3]);
    *(float4*)&out[base + 4] = make_float4(o[4], o[5], o[6], o[7]);
}

// ---------------- launch -------------------------------------------------
template <typename T>
static inline T* sym(const void* s)
{
    void* p = nullptr;
    cudaGetSymbolAddress(&p, s);
    return (T*)p;
}

extern "C" void kernel_launch(void* const* d_in, const int* in_sizes, int n_in,
                              void* d_out, int out_size)
{
    const float* src     = (const float*)d_in[0];
    const float* pos     = (const float*)d_in[1];
    const float* w_value = (const float*)d_in[4];
    const float* b_value = (const float*)d_in[5];
    const float* w_off   = (const float*)d_in[6];
    const float* b_off   = (const float*)d_in[7];
    const float* w_attn  = (const float*)d_in[8];
    const float* b_attn  = (const float*)d_in[9];
    const float* w_out   = (const float*)d_in[10];
    const float* b_out   = (const float*)d_in[11];
    const float* w1      = (const float*)d_in[12];
    const float* b1      = (const float*)d_in[13];
    const float* w2      = (const float*)d_in[14];
    const float* b2      = (const float*)d_in[15];
    const float* g1      = (const float*)d_in[16];
    const float* be1     = (const float*)d_in[17];
    const float* g2      = (const float*)d_in[18];
    const float* be2     = (const float*)d_in[19];
    float* out = (float*)d_out;

    __half* valh    = sym<__half>(g_valh);
    float*  offattn = sym<float>(g_offattn);
    __half* out2    = sym<__half>(g_out2);
    float*  x       = sym<float>(g_x);
    __half* part    = sym<__half>(g_part);
    float*  boa     = sym<float>(g_boa);
    __half* srch    = sym<__half>(g_srch);
    __half* qh      = sym<__half>(g_qh);
    __half* samph   = sym<__half>(g_samph);
    __half* xh      = sym<__half>(g_xh);
    __half* ffhh    = sym<__half>(g_ffhh);
    __half* wvT     = sym<__half>(g_wvT);
    __half* woaT    = sym<__half>(g_woaT);
    __half* woutT   = sym<__half>(g_woutT);
    __half* w1T     = sym<__half>(g_w1T);
    __half* w2T     = sym<__half>(g_w2T);

    cudaFuncSetAttribute(gemm_mma<1, __half>, cudaFuncAttributeMaxDynamicSharedMemorySize, SMBYTES);
    cudaFuncSetAttribute(gemm_mma<2, __half>, cudaFuncAttributeMaxDynamicSharedMemorySize, SMBYTES);
    cudaFuncSetAttribute(gemm_dual,           cudaFuncAttributeMaxDynamicSharedMemorySize, SMBYTES);

    // prep: addcvt (2720) + transposes (1248) + bias concat (1)
    prep_kernel<<<PREP_BLKS, 256>>>((const float4*)src, (const float4*)pos,
                                    (__half2*)qh, (__half2*)srch,
                                    w_value, w_off, w_attn, w_out, w1, w2,
                                    wvT, woaT, woutT, w1T, w2T,
                                    b_off, b_attn, boa);

    // value proj (fp16 out) + off/attn proj (fp32 out), one launch
    gemm_dual<<<dim3(5, M_TOK / 128), 256, SMBYTES>>>(srch, qh, wvT, woaT,
                                                      valh, offattn, b_value, boa);

    // deformable sampling (softmax fused, precompute+gather)
    sample_kernel<<<M_TOK, 256>>>(valh, offattn, samph);

    // output projection: 128x64 tiles, 3 CTAs/SM, fp16 out
    gemm64_bias<<<dim3(4, M_TOK / 128), 256, SMBYTES6>>>(
        samph, 256, woutT, 256, out2, 256, b_out, 256);

    // x = LN(src + out2), warp-per-row
    add_ln_kernel<<<M_TOK / 8, 256>>>(src, out2, g1, be1, x, xh);

    // FFN1: relu(x @ w1 + b1), fp16 out
    gemm_mma<1, __half><<<dim3(16, M_TOK / 128), 256, SMBYTES>>>(
        xh, 256, w1T, 256, ffhh, DFF, 0, b1, 256);

    // FFN2: split-K=4 fp16 partials (kLen=512 each)
    gemm_mma<2, __half><<<dim3(2, M_TOK / 128, 4), 256, SMBYTES>>>(
        ffhh, DFF, w2T, DFF, part, 256, (size_t)M_TOK * 256, nullptr, 512);

    // out = LN(x + sum(parts) + b2), warp-per-row
    add4_ln_kernel<<<M_TOK / 8, 256>>>(x, part, b2, g2, be2, out);
}